// round 13
// baseline (speedup 1.0000x reference)
#include <cuda_runtime.h>
#include <cuda_fp16.h>
#include <cstdint>

// LIF spiking layer, monitor='mem'
//   inputs: [B=64, T=1024, IN=256] f32   (d_in[0])
//   w:      [IN=256, OUT=256] f32        (d_in[1])
//   out U:  [B=64, T=1024, OUT=256] f32  (d_out)
//
// Stage 0: prep — split W into 2 fp16 limbs, packed in m16n8k16 B-fragment order.
// Stage 1: 3xFP16 GEMM: main product a0b0 in f32-accum HMMA, corrections
//          a0b1 + a1b0 share ONE f16-accum HMMA accumulator (2x issue rate).
// Stage 2: in-place LIF scan, 256 CTAs x 64 threads.

// ---------------------------------------------------------------------------
// helpers
// ---------------------------------------------------------------------------
__device__ __forceinline__ void cp_async16(uint32_t smem_addr, const void* gptr) {
    asm volatile("cp.async.cg.shared.global [%0], [%1], 16;"
                 :: "r"(smem_addr), "l"(gptr) : "memory");
}
__device__ __forceinline__ void cp_async_commit() {
    asm volatile("cp.async.commit_group;" ::: "memory");
}
template <int N>
__device__ __forceinline__ void cp_async_wait() {
    asm volatile("cp.async.wait_group %0;" :: "n"(N) : "memory");
}
__device__ __forceinline__ uint32_t smem_u32(const void* p) {
    uint32_t a;
    asm("{ .reg .u64 t; cvta.to.shared.u64 t, %1; cvt.u32.u64 %0, t; }"
        : "=r"(a) : "l"(p));
    return a;
}
__device__ __forceinline__ void mma_f16_f32acc(float* c, const uint32_t* a,
                                               uint32_t b0, uint32_t b1) {
    asm volatile(
        "mma.sync.aligned.m16n8k16.row.col.f32.f16.f16.f32 "
        "{%0,%1,%2,%3}, {%4,%5,%6,%7}, {%8,%9}, {%0,%1,%2,%3};"
        : "+f"(c[0]), "+f"(c[1]), "+f"(c[2]), "+f"(c[3])
        : "r"(a[0]), "r"(a[1]), "r"(a[2]), "r"(a[3]), "r"(b0), "r"(b1));
}
__device__ __forceinline__ void mma_f16_f16acc(uint32_t* c, const uint32_t* a,
                                               uint32_t b0, uint32_t b1) {
    asm volatile(
        "mma.sync.aligned.m16n8k16.row.col.f16.f16.f16.f16 "
        "{%0,%1}, {%2,%3,%4,%5}, {%6,%7}, {%0,%1};"
        : "+r"(c[0]), "+r"(c[1])
        : "r"(a[0]), "r"(a[1]), "r"(a[2]), "r"(a[3]), "r"(b0), "r"(b1));
}

// B fragments: [h(2)][nt(16)][k16(16)][lane(32)][l0b0,l0b1,l1b0,l1b1] = 256KB
__device__ __align__(16) unsigned char g_Bfrag[2 * 16 * 16 * 32 * 16];

// ---------------------------------------------------------------------------
// Stage 0: W -> fp16 limb fragments (m16n8k16 B layout, col-major B).
// ---------------------------------------------------------------------------
__global__ void prep_w_kernel(const float* __restrict__ w) {
    int idx = blockIdx.x * blockDim.x + threadIdx.x;  // 0..65535
    int k = idx >> 8;
    int n = idx & 255;
    float v = w[k * 256 + n];
    __half h0 = __float2half_rn(v);
    __half h1 = __float2half_rn(v - __half2float(h0));

    int h = n >> 7, n_ = n & 127;
    int nt = n_ >> 3, g = n_ & 7;
    int k16 = k >> 4, kk = k & 15;
    int t = (kk & 7) >> 1;
    int reg = (kk & 8) >> 3;
    int hs = kk & 1;
    int lane = g * 4 + t;
    unsigned char* base =
        &g_Bfrag[((((size_t)h * 16 + nt) * 16 + k16) * 32 + lane) * 16];
    *(__half*)(base + reg * 4 + hs * 2)     = h0;   // limb0: b0,b1
    *(__half*)(base + 8 + reg * 4 + hs * 2) = h1;   // limb1: b0,b1
}

// ---------------------------------------------------------------------------
// Stage 1: GEMM. Grid 1024 = 512 mtiles x 2 n-halves. 256 threads.
// Per stage (BK=32): A 16KB, B 16KB. 3-stage circular buffer (96KB).
// ---------------------------------------------------------------------------
constexpr int A_STAGE     = 16384;
constexpr int STAGE_BYTES = 32768;
constexpr int NSTAGE      = 3;
constexpr int GEMM_SMEM   = NSTAGE * STAGE_BYTES;   // 96KB

struct ARegs { float4 lo[2], hi[2]; };  // two tasks x (row g, row g+8)

__device__ __forceinline__ void ldA(const float* __restrict__ A, int mtile,
                                    int s, int tid, ARegs& rg) {
#pragma unroll
    for (int q = 0; q < 2; ++q) {
        int tau = tid + q * 256;         // 0..511
        int cc  = tau & 7;               // col chunk (4 floats within 32-col stage)
        int pid = tau >> 3;              // 0..63
        int mtg = pid >> 3, g = pid & 7;
        const float* p = A + (size_t)(mtile * 128 + mtg * 16 + g) * 256 + s * 32 + cc * 4;
        rg.lo[q] = *(const float4*)p;
        rg.hi[q] = *(const float4*)(p + 8 * 256);
    }
}

__device__ __forceinline__ void stA(char* abuf, int tid, const ARegs& rg) {
#pragma unroll
    for (int q = 0; q < 2; ++q) {
        int tau = tid + q * 256;
        int cc  = tau & 7;
        int pid = tau >> 3;
        int mtg = pid >> 3, g = pid & 7;
        int k16l = cc >> 2;
        int kk0  = (cc & 3) * 4;
        char* blk = abuf + (mtg * 2 + k16l) * 1024;
        const float* lo = (const float*)&rg.lo[q];
        const float* hi = (const float*)&rg.hi[q];
#pragma unroll
        for (int p = 0; p < 2; ++p) {
            int kk = kk0 + 2 * p;
            int t = (kk & 7) >> 1;
            int koff = kk & 8;
            int lane = g * 4 + t;
            float v00 = lo[2 * p], v01 = lo[2 * p + 1];
            float v10 = hi[2 * p], v11 = hi[2 * p + 1];
            __half a00 = __float2half_rn(v00), a01 = __float2half_rn(v01);
            __half a10 = __float2half_rn(v10), a11 = __float2half_rn(v11);
            __half b00 = __float2half_rn(v00 - __half2float(a00));
            __half b01 = __float2half_rn(v01 - __half2float(a01));
            __half b10 = __float2half_rn(v10 - __half2float(a10));
            __half b11 = __float2half_rn(v11 - __half2float(a11));
            __half2 l0g  = __halves2half2(a00, a01);
            __half2 l0g8 = __halves2half2(a10, a11);
            __half2 l1g  = __halves2half2(b00, b01);
            __half2 l1g8 = __halves2half2(b10, b11);
            *(uint2*)(blk + lane * 16 + koff) =
                make_uint2(*(uint32_t*)&l0g, *(uint32_t*)&l0g8);
            *(uint2*)(blk + 512 + lane * 16 + koff) =
                make_uint2(*(uint32_t*)&l1g, *(uint32_t*)&l1g8);
        }
    }
}

__device__ __forceinline__ void cpB(uint32_t bbuf, int h, int s, int tid) {
#pragma unroll
    for (int i = 0; i < 4; ++i) {
        int q = tid + i * 256;           // 0..1023: nt*64 + k16l*32 + lane
        int lane = q & 31;
        int k16l = (q >> 5) & 1;
        int nt   = q >> 6;
        const unsigned char* src =
            g_Bfrag + ((((size_t)h * 16 + nt) * 16 + (2 * s + k16l)) * 32 + lane) * 16;
        cp_async16(bbuf + q * 16, src);
    }
    cp_async_commit();
}

__global__ __launch_bounds__(256) void gemm_tc_kernel(
    const float* __restrict__ A, float* __restrict__ out)
{
    extern __shared__ char smem[];
    const int tid    = threadIdx.x;
    const int wid    = tid >> 5;
    const int lane   = tid & 31;
    const int warp_m = wid & 3;        // 4 x 32 rows
    const int warp_n = wid >> 2;       // 2 x 64 cols
    const int mtile  = blockIdx.x >> 1;
    const int h      = blockIdx.x & 1;

    const uint32_t sbase = smem_u32(smem);

    float    accM[2][8][4];            // main a0b0, f32 accum
    uint32_t accC[2][8][2];            // corrections a0b1 + a1b0, f16x2 accum
#pragma unroll
    for (int i = 0; i < 2; ++i)
#pragma unroll
        for (int j = 0; j < 8; ++j) {
#pragma unroll
            for (int k = 0; k < 4; ++k) accM[i][j][k] = 0.0f;
            accC[i][j][0] = 0u; accC[i][j][1] = 0u;
        }

    ARegs rg;
    // prologue: B for stages 0,1 in flight; A stage 0 staged
    cpB(sbase + 0 * STAGE_BYTES + A_STAGE, h, 0, tid);
    cpB(sbase + 1 * STAGE_BYTES + A_STAGE, h, 1, tid);
    ldA(A, mtile, 0, tid, rg);
    stA(smem + 0 * STAGE_BYTES, tid, rg);
    cp_async_wait<1>();                 // B0 resident
    __syncthreads();

    for (int s = 0; s < 8; ++s) {
        const int buf  = s % NSTAGE;
        const int nbuf = (s + 1) % NSTAGE;
        const int pbuf = (s + 2) % NSTAGE;
        char* cbuf = smem + buf * STAGE_BYTES;

        if (s + 2 < 8)
            cpB(sbase + pbuf * STAGE_BYTES + A_STAGE, h, s + 2, tid);
        if (s + 1 < 8) {
            ldA(A, mtile, s + 1, tid, rg);
            stA(smem + nbuf * STAGE_BYTES, tid, rg);
        }

#pragma unroll
        for (int k16l = 0; k16l < 2; ++k16l) {
            uint4 afr[2][2];
#pragma unroll
            for (int mtl = 0; mtl < 2; ++mtl) {
                int mtg = warp_m * 2 + mtl;
                char* blk = cbuf + (mtg * 2 + k16l) * 1024;
                afr[mtl][0] = *(uint4*)(blk + lane * 16);
                afr[mtl][1] = *(uint4*)(blk + 512 + lane * 16);
            }
#pragma unroll
            for (int ng = 0; ng < 2; ++ng) {
                uint4 bfr[4];
#pragma unroll
                for (int j = 0; j < 4; ++j) {
                    int nt = warp_n * 8 + ng * 4 + j;
                    bfr[j] = *(uint4*)(cbuf + A_STAGE +
                                       ((nt * 2 + k16l) * 32 + lane) * 16);
                }
#pragma unroll
                for (int mtl = 0; mtl < 2; ++mtl)
#pragma unroll
                    for (int j = 0; j < 4; ++j) {
                        int nn = ng * 4 + j;
                        mma_f16_f32acc(accM[mtl][nn],
                                       (const uint32_t*)&afr[mtl][0],
                                       bfr[j].x, bfr[j].y);          // a0*b0
                        mma_f16_f16acc(accC[mtl][nn],
                                       (const uint32_t*)&afr[mtl][0],
                                       bfr[j].z, bfr[j].w);          // a0*b1
                        mma_f16_f16acc(accC[mtl][nn],
                                       (const uint32_t*)&afr[mtl][1],
                                       bfr[j].x, bfr[j].y);          // a1*b0
                    }
            }
        }

        if (s + 2 < 8)      cp_async_wait<1>();
        else if (s + 1 < 8) cp_async_wait<0>();
        __syncthreads();
    }

    // epilogue: c0=(g,2t) c1=(g,2t+1) c2=(g+8,2t) c3=(g+8,2t+1)
    // f16 accum frag: c[0]=half2(g,2t | g,2t+1), c[1]=half2(g+8,2t | g+8,2t+1)
    const int g = lane >> 2, t = lane & 3;
#pragma unroll
    for (int mtl = 0; mtl < 2; ++mtl) {
        int row0 = mtile * 128 + warp_m * 32 + mtl * 16 + g;
#pragma unroll
        for (int ntl = 0; ntl < 8; ++ntl) {
            int col = h * 128 + warp_n * 64 + ntl * 8 + 2 * t;
            float2 c0 = __half22float2(*(__half2*)&accC[mtl][ntl][0]);
            float2 c1 = __half22float2(*(__half2*)&accC[mtl][ntl][1]);
            *(float2*)(out + (size_t)row0 * 256 + col) =
                make_float2(accM[mtl][ntl][0] + c0.x, accM[mtl][ntl][1] + c0.y);
            *(float2*)(out + (size_t)(row0 + 8) * 256 + col) =
                make_float2(accM[mtl][ntl][2] + c1.x, accM[mtl][ntl][3] + c1.y);
        }
    }
}

// ---------------------------------------------------------------------------
// Stage 2: in-place LIF scan. 256 CTAs x 64 threads (b x o-quarter).
// ---------------------------------------------------------------------------
constexpr int T_STEPS = 1024;
constexpr int OUT_C   = 256;
constexpr int TS      = 32;
constexpr int LPB     = 64;
constexpr int NTILES  = T_STEPS / TS;
constexpr int PIPE    = 2;

__global__ __launch_bounds__(LPB) void lif_scan_kernel(float* __restrict__ X)
{
    __shared__ float tile[PIPE][TS * LPB];   // 2 x 8KB

    const int tid = threadIdx.x;
    const int b   = blockIdx.x >> 2;
    const int qt  = blockIdx.x & 3;
    float* base  = X + (size_t)b * T_STEPS * OUT_C + qt * LPB;
    float* gbase = base + tid;

    uint32_t smem_base = smem_u32(&tile[0][0]);

    auto issue_tile = [&](int c, int stage) {
#pragma unroll
        for (int k = 0; k < 8; ++k) {
            int chunk = tid + k * LPB;
            int row   = chunk >> 4;
            int c16   = chunk & 15;
            const void* g = (const char*)base +
                (size_t)(c * TS + row) * OUT_C * 4 + c16 * 16;
            uint32_t s = smem_base + stage * (TS * LPB * 4) + row * (LPB * 4) + c16 * 16;
            cp_async16(s, g);
        }
        cp_async_commit();
    };

    issue_tile(0, 0);
    issue_tile(1, 1);

    const float dcy_syn = 0.81873075307798185867f;   // exp(-0.2)
    const float dcy_mem = 0.90483741803595957316f;   // exp(-0.1)
    const float scl_mem = 1.0f - dcy_mem;

    float syn = 0.0f, mem = 0.0f;
    float carry = 0.0f;

    for (int c = 0; c < NTILES; ++c) {
        const int stage = c & (PIPE - 1);
        if (c == NTILES - 1) cp_async_wait<0>();
        else                 cp_async_wait<PIPE - 1>();
        __syncthreads();

        gbase[(size_t)(c * TS) * OUT_C] = carry;

        const float* sm = &tile[stage][tid];
#pragma unroll
        for (int i = 0; i < TS; ++i) {
            const int t = c * TS + i;
            if (t < T_STEPS - 1) {
                const float x    = sm[i * LPB];
                const float nsyn = fmaf(dcy_syn, syn, x);
                float nmem = fmaf(dcy_mem, mem, scl_mem * syn);
                if (mem > 1.0f) nmem = 0.0f;
                if (i < TS - 1)
                    gbase[(size_t)(t + 1) * OUT_C] = nmem;
                else
                    carry = nmem;
                syn = nsyn;
                mem = nmem;
            }
        }

        __syncthreads();
        if (c + PIPE < NTILES)
            issue_tile(c + PIPE, stage);
    }
}

// ---------------------------------------------------------------------------
extern "C" void kernel_launch(void* const* d_in, const int* in_sizes, int n_in,
                              void* d_out, int out_size)
{
    const float* inputs = (const float*)d_in[0];  // [64,1024,256]
    const float* w      = (const float*)d_in[1];  // [256,256]
    float* out          = (float*)d_out;          // [64,1024,256]

    cudaFuncSetAttribute(gemm_tc_kernel,
                         cudaFuncAttributeMaxDynamicSharedMemorySize, GEMM_SMEM);

    // Stage 0: W -> fp16 limb fragments
    prep_w_kernel<<<256, 256>>>(w);

    // Stage 1: x = inputs @ w -> d_out
    gemm_tc_kernel<<<1024, 256, GEMM_SMEM>>>(inputs, out);

    // Stage 2: in-place scan x -> U
    lif_scan_kernel<<<64 * 4, LPB>>>(out);
}

// round 14
// speedup vs baseline: 1.3074x; 1.3074x over previous
#include <cuda_runtime.h>
#include <cuda_fp16.h>
#include <cstdint>

// LIF spiking layer, monitor='mem'
//   inputs: [B=64, T=1024, IN=256] f32   (d_in[0])
//   w:      [IN=256, OUT=256] f32        (d_in[1])
//   out U:  [B=64, T=1024, OUT=256] f32  (d_out)
//
// Stage 0: prep — split W into 2 fp16 limbs, packed in m16n8k16 B-fragment order.
// Stage 1: 3xFP16 GEMM (all f32-accum HMMA — R12 proven, ~95% of HMMA floor).
// Stage 2: in-place LIF scan, 256 CTAs x 64 threads, 3-stage cp.async pipeline.

// ---------------------------------------------------------------------------
// helpers
// ---------------------------------------------------------------------------
__device__ __forceinline__ void cp_async16(uint32_t smem_addr, const void* gptr) {
    asm volatile("cp.async.cg.shared.global [%0], [%1], 16;"
                 :: "r"(smem_addr), "l"(gptr) : "memory");
}
__device__ __forceinline__ void cp_async_commit() {
    asm volatile("cp.async.commit_group;" ::: "memory");
}
template <int N>
__device__ __forceinline__ void cp_async_wait() {
    asm volatile("cp.async.wait_group %0;" :: "n"(N) : "memory");
}
__device__ __forceinline__ uint32_t smem_u32(const void* p) {
    uint32_t a;
    asm("{ .reg .u64 t; cvta.to.shared.u64 t, %1; cvt.u32.u64 %0, t; }"
        : "=r"(a) : "l"(p));
    return a;
}
__device__ __forceinline__ void mma_f16(float* c, const uint32_t* a,
                                        uint32_t b0, uint32_t b1) {
    asm volatile(
        "mma.sync.aligned.m16n8k16.row.col.f32.f16.f16.f32 "
        "{%0,%1,%2,%3}, {%4,%5,%6,%7}, {%8,%9}, {%0,%1,%2,%3};"
        : "+f"(c[0]), "+f"(c[1]), "+f"(c[2]), "+f"(c[3])
        : "r"(a[0]), "r"(a[1]), "r"(a[2]), "r"(a[3]), "r"(b0), "r"(b1));
}

// B fragments: [h(2)][nt(16)][k16(16)][lane(32)][l0b0,l0b1,l1b0,l1b1] = 256KB
__device__ __align__(16) unsigned char g_Bfrag[2 * 16 * 16 * 32 * 16];

// ---------------------------------------------------------------------------
// Stage 0: W -> fp16 limb fragments (m16n8k16 B layout, col-major B).
// ---------------------------------------------------------------------------
__global__ void prep_w_kernel(const float* __restrict__ w) {
    int idx = blockIdx.x * blockDim.x + threadIdx.x;  // 0..65535
    int k = idx >> 8;
    int n = idx & 255;
    float v = w[k * 256 + n];
    __half h0 = __float2half_rn(v);
    __half h1 = __float2half_rn(v - __half2float(h0));

    int h = n >> 7, n_ = n & 127;
    int nt = n_ >> 3, g = n_ & 7;
    int k16 = k >> 4, kk = k & 15;
    int t = (kk & 7) >> 1;
    int reg = (kk & 8) >> 3;
    int hs = kk & 1;
    int lane = g * 4 + t;
    unsigned char* base =
        &g_Bfrag[((((size_t)h * 16 + nt) * 16 + k16) * 32 + lane) * 16];
    *(__half*)(base + reg * 4 + hs * 2)     = h0;   // limb0: b0,b1
    *(__half*)(base + 8 + reg * 4 + hs * 2) = h1;   // limb1: b0,b1
}

// ---------------------------------------------------------------------------
// Stage 1: 3xFP16 GEMM. Grid 1024 = 512 mtiles x 2 n-halves. 256 threads.
// Per stage (BK=32): A 16KB, B 16KB. 3-stage circular buffer (96KB), 2 CTAs/SM.
// ---------------------------------------------------------------------------
constexpr int A_STAGE     = 16384;
constexpr int STAGE_BYTES = 32768;
constexpr int NSTAGE      = 3;
constexpr int GEMM_SMEM   = NSTAGE * STAGE_BYTES;   // 96KB

struct ARegs { float4 lo[2], hi[2]; };  // two tasks x (row g, row g+8)

__device__ __forceinline__ void ldA(const float* __restrict__ A, int mtile,
                                    int s, int tid, ARegs& rg) {
#pragma unroll
    for (int q = 0; q < 2; ++q) {
        int tau = tid + q * 256;         // 0..511
        int cc  = tau & 7;               // col chunk (4 floats within 32-col stage)
        int pid = tau >> 3;              // 0..63
        int mtg = pid >> 3, g = pid & 7;
        const float* p = A + (size_t)(mtile * 128 + mtg * 16 + g) * 256 + s * 32 + cc * 4;
        rg.lo[q] = *(const float4*)p;
        rg.hi[q] = *(const float4*)(p + 8 * 256);
    }
}

__device__ __forceinline__ void stA(char* abuf, int tid, const ARegs& rg) {
#pragma unroll
    for (int q = 0; q < 2; ++q) {
        int tau = tid + q * 256;
        int cc  = tau & 7;
        int pid = tau >> 3;
        int mtg = pid >> 3, g = pid & 7;
        int k16l = cc >> 2;
        int kk0  = (cc & 3) * 4;
        char* blk = abuf + (mtg * 2 + k16l) * 1024;
        const float* lo = (const float*)&rg.lo[q];
        const float* hi = (const float*)&rg.hi[q];
#pragma unroll
        for (int p = 0; p < 2; ++p) {
            int kk = kk0 + 2 * p;
            int t = (kk & 7) >> 1;
            int koff = kk & 8;
            int lane = g * 4 + t;
            float v00 = lo[2 * p], v01 = lo[2 * p + 1];
            float v10 = hi[2 * p], v11 = hi[2 * p + 1];
            __half a00 = __float2half_rn(v00), a01 = __float2half_rn(v01);
            __half a10 = __float2half_rn(v10), a11 = __float2half_rn(v11);
            __half b00 = __float2half_rn(v00 - __half2float(a00));
            __half b01 = __float2half_rn(v01 - __half2float(a01));
            __half b10 = __float2half_rn(v10 - __half2float(a10));
            __half b11 = __float2half_rn(v11 - __half2float(a11));
            __half2 l0g  = __halves2half2(a00, a01);
            __half2 l0g8 = __halves2half2(a10, a11);
            __half2 l1g  = __halves2half2(b00, b01);
            __half2 l1g8 = __halves2half2(b10, b11);
            *(uint2*)(blk + lane * 16 + koff) =
                make_uint2(*(uint32_t*)&l0g, *(uint32_t*)&l0g8);
            *(uint2*)(blk + 512 + lane * 16 + koff) =
                make_uint2(*(uint32_t*)&l1g, *(uint32_t*)&l1g8);
        }
    }
}

__device__ __forceinline__ void cpB(uint32_t bbuf, int h, int s, int tid) {
#pragma unroll
    for (int i = 0; i < 4; ++i) {
        int q = tid + i * 256;           // 0..1023: nt*64 + k16l*32 + lane
        int lane = q & 31;
        int k16l = (q >> 5) & 1;
        int nt   = q >> 6;
        const unsigned char* src =
            g_Bfrag + ((((size_t)h * 16 + nt) * 16 + (2 * s + k16l)) * 32 + lane) * 16;
        cp_async16(bbuf + q * 16, src);
    }
    cp_async_commit();
}

__global__ __launch_bounds__(256, 2) void gemm_tc_kernel(
    const float* __restrict__ A, float* __restrict__ out)
{
    extern __shared__ char smem[];
    const int tid    = threadIdx.x;
    const int wid    = tid >> 5;
    const int lane   = tid & 31;
    const int warp_m = wid & 3;        // 4 x 32 rows
    const int warp_n = wid >> 2;       // 2 x 64 cols
    const int mtile  = blockIdx.x >> 1;
    const int h      = blockIdx.x & 1;

    const uint32_t sbase = smem_u32(smem);

    float acc[2][8][4];
#pragma unroll
    for (int i = 0; i < 2; ++i)
#pragma unroll
        for (int j = 0; j < 8; ++j)
#pragma unroll
            for (int k = 0; k < 4; ++k) acc[i][j][k] = 0.0f;

    ARegs rg;
    // prologue: B for stages 0,1 in flight; A stage 0 staged
    cpB(sbase + 0 * STAGE_BYTES + A_STAGE, h, 0, tid);
    cpB(sbase + 1 * STAGE_BYTES + A_STAGE, h, 1, tid);
    ldA(A, mtile, 0, tid, rg);
    stA(smem + 0 * STAGE_BYTES, tid, rg);
    cp_async_wait<1>();                 // B0 resident
    __syncthreads();

    for (int s = 0; s < 8; ++s) {
        const int buf  = s % NSTAGE;
        const int nbuf = (s + 1) % NSTAGE;
        const int pbuf = (s + 2) % NSTAGE;
        char* cbuf = smem + buf * STAGE_BYTES;

        if (s + 2 < 8)
            cpB(sbase + pbuf * STAGE_BYTES + A_STAGE, h, s + 2, tid);
        if (s + 1 < 8) {
            ldA(A, mtile, s + 1, tid, rg);
            stA(smem + nbuf * STAGE_BYTES, tid, rg);   // frees rg before MMAs
        }

#pragma unroll
        for (int k16l = 0; k16l < 2; ++k16l) {
            uint4 afr[2][2];
#pragma unroll
            for (int mtl = 0; mtl < 2; ++mtl) {
                int mtg = warp_m * 2 + mtl;
                char* blk = cbuf + (mtg * 2 + k16l) * 1024;
                afr[mtl][0] = *(uint4*)(blk + lane * 16);
                afr[mtl][1] = *(uint4*)(blk + 512 + lane * 16);
            }
#pragma unroll
            for (int ng = 0; ng < 2; ++ng) {       // keep only 4 B-frags live
                uint4 bfr[4];
#pragma unroll
                for (int j = 0; j < 4; ++j) {
                    int nt = warp_n * 8 + ng * 4 + j;
                    bfr[j] = *(uint4*)(cbuf + A_STAGE +
                                       ((nt * 2 + k16l) * 32 + lane) * 16);
                }
#pragma unroll
                for (int mtl = 0; mtl < 2; ++mtl)
#pragma unroll
                    for (int j = 0; j < 4; ++j) {
                        float* c = acc[mtl][ng * 4 + j];
                        mma_f16(c, (const uint32_t*)&afr[mtl][0], bfr[j].x, bfr[j].y);
                        mma_f16(c, (const uint32_t*)&afr[mtl][0], bfr[j].z, bfr[j].w);
                        mma_f16(c, (const uint32_t*)&afr[mtl][1], bfr[j].x, bfr[j].y);
                    }
            }
        }

        if (s + 2 < 8)      cp_async_wait<1>();    // B(s+1) resident
        else if (s + 1 < 8) cp_async_wait<0>();    // last prefetch drains
        __syncthreads();
    }

    // epilogue: c0=(g,2t) c1=(g,2t+1) c2=(g+8,2t) c3=(g+8,2t+1)
    const int g = lane >> 2, t = lane & 3;
#pragma unroll
    for (int mtl = 0; mtl < 2; ++mtl) {
        int row0 = mtile * 128 + warp_m * 32 + mtl * 16 + g;
#pragma unroll
        for (int ntl = 0; ntl < 8; ++ntl) {
            int col = h * 128 + warp_n * 64 + ntl * 8 + 2 * t;
            *(float2*)(out + (size_t)row0 * 256 + col) =
                make_float2(acc[mtl][ntl][0], acc[mtl][ntl][1]);
            *(float2*)(out + (size_t)(row0 + 8) * 256 + col) =
                make_float2(acc[mtl][ntl][2], acc[mtl][ntl][3]);
        }
    }
}

// ---------------------------------------------------------------------------
// Stage 2: in-place LIF scan. 256 CTAs x 64 threads (b x o-quarter),
// 3-stage cp.async pipeline (prefetch distance 2).
//
// Group accounting: tiles 0..2 primed; tile j committed at end of iter j-3.
// At iter c, committed = min(c+3, NTILES). Tile c resident requires
// pending <= committed-(c+1): c+3 <= NTILES -> wait<2>, else wait<0>
// (conservative for the last two iterations).
//
// In-place safety: tile c's U writes touch rows c*TS..(c+1)*TS-1 only;
// tiles c+2/c+3 load rows >= (c+2)*TS, which are first written at
// iterations c+2/c+3 after those loads completed.
// ---------------------------------------------------------------------------
constexpr int T_STEPS = 1024;
constexpr int OUT_C   = 256;
constexpr int TS      = 32;
constexpr int LPB     = 64;
constexpr int NTILES  = T_STEPS / TS;       // 32
constexpr int SPIPE   = 3;

__global__ __launch_bounds__(LPB) void lif_scan_kernel(float* __restrict__ X)
{
    __shared__ float tile[SPIPE][TS * LPB];   // 3 x 8KB

    const int tid = threadIdx.x;
    const int b   = blockIdx.x >> 2;
    const int qt  = blockIdx.x & 3;
    float* base  = X + (size_t)b * T_STEPS * OUT_C + qt * LPB;
    float* gbase = base + tid;

    uint32_t smem_base = smem_u32(&tile[0][0]);

    // per tile: 32 rows x 16 x 16B chunks = 512 chunks, 64 threads x 8
    auto issue_tile = [&](int c, int stage) {
#pragma unroll
        for (int k = 0; k < 8; ++k) {
            int chunk = tid + k * LPB;
            int row   = chunk >> 4;
            int c16   = chunk & 15;
            const void* g = (const char*)base +
                (size_t)(c * TS + row) * OUT_C * 4 + c16 * 16;
            uint32_t s = smem_base + stage * (TS * LPB * 4) + row * (LPB * 4) + c16 * 16;
            cp_async16(s, g);
        }
        cp_async_commit();
    };

    issue_tile(0, 0);
    issue_tile(1, 1);
    issue_tile(2, 2);

    const float dcy_syn = 0.81873075307798185867f;   // exp(-0.2)
    const float dcy_mem = 0.90483741803595957316f;   // exp(-0.1)
    const float scl_mem = 1.0f - dcy_mem;

    float syn = 0.0f, mem = 0.0f;
    float carry = 0.0f;

    int stage = 0;
    for (int c = 0; c < NTILES; ++c) {
        if (c + SPIPE <= NTILES) cp_async_wait<SPIPE - 1>();
        else                     cp_async_wait<0>();
        __syncthreads();

        gbase[(size_t)(c * TS) * OUT_C] = carry;

        const float* sm = &tile[stage][tid];
#pragma unroll
        for (int i = 0; i < TS; ++i) {
            const int t = c * TS + i;
            if (t < T_STEPS - 1) {
                const float x    = sm[i * LPB];
                const float nsyn = fmaf(dcy_syn, syn, x);
                float nmem = fmaf(dcy_mem, mem, scl_mem * syn);
                if (mem > 1.0f) nmem = 0.0f;
                if (i < TS - 1)
                    gbase[(size_t)(t + 1) * OUT_C] = nmem;
                else
                    carry = nmem;
                syn = nsyn;
                mem = nmem;
            }
        }

        __syncthreads();
        if (c + SPIPE < NTILES)
            issue_tile(c + SPIPE, stage);
        stage = (stage + 1 == SPIPE) ? 0 : stage + 1;
    }
}

// ---------------------------------------------------------------------------
extern "C" void kernel_launch(void* const* d_in, const int* in_sizes, int n_in,
                              void* d_out, int out_size)
{
    const float* inputs = (const float*)d_in[0];  // [64,1024,256]
    const float* w      = (const float*)d_in[1];  // [256,256]
    float* out          = (float*)d_out;          // [64,1024,256]

    cudaFuncSetAttribute(gemm_tc_kernel,
                         cudaFuncAttributeMaxDynamicSharedMemorySize, GEMM_SMEM);

    // Stage 0: W -> fp16 limb fragments
    prep_w_kernel<<<256, 256>>>(w);

    // Stage 1: x = inputs @ w -> d_out (3xFP16 mma.sync m16n8k16, f32 accum)
    gemm_tc_kernel<<<1024, 256, GEMM_SMEM>>>(inputs, out);

    // Stage 2: in-place scan x -> U
    lif_scan_kernel<<<64 * 4, LPB>>>(out);
}

// round 15
// speedup vs baseline: 1.3097x; 1.0017x over previous
#include <cuda_runtime.h>
#include <cuda_fp16.h>
#include <cstdint>

// LIF spiking layer, monitor='mem'
//   inputs: [B=64, T=1024, IN=256] f32   (d_in[0])
//   w:      [IN=256, OUT=256] f32        (d_in[1])
//   out U:  [B=64, T=1024, OUT=256] f32  (d_out)
//
// Stage 1: 3xFP16 GEMM (f32-accum mma.sync.m16n8k16), W converted to fp16
//          limb fragments IN-KERNEL per stage (no prep launch).
// Stage 2: in-place LIF scan, 256 CTAs x 64 threads, 3-stage cp.async pipeline.

// ---------------------------------------------------------------------------
// helpers
// ---------------------------------------------------------------------------
__device__ __forceinline__ void cp_async16(uint32_t smem_addr, const void* gptr) {
    asm volatile("cp.async.cg.shared.global [%0], [%1], 16;"
                 :: "r"(smem_addr), "l"(gptr) : "memory");
}
__device__ __forceinline__ void cp_async_commit() {
    asm volatile("cp.async.commit_group;" ::: "memory");
}
template <int N>
__device__ __forceinline__ void cp_async_wait() {
    asm volatile("cp.async.wait_group %0;" :: "n"(N) : "memory");
}
__device__ __forceinline__ uint32_t smem_u32(const void* p) {
    uint32_t a;
    asm("{ .reg .u64 t; cvta.to.shared.u64 t, %1; cvt.u32.u64 %0, t; }"
        : "=r"(a) : "l"(p));
    return a;
}
__device__ __forceinline__ void mma_f16(float* c, const uint32_t* a,
                                        uint32_t b0, uint32_t b1) {
    asm volatile(
        "mma.sync.aligned.m16n8k16.row.col.f32.f16.f16.f32 "
        "{%0,%1,%2,%3}, {%4,%5,%6,%7}, {%8,%9}, {%0,%1,%2,%3};"
        : "+f"(c[0]), "+f"(c[1]), "+f"(c[2]), "+f"(c[3])
        : "r"(a[0]), "r"(a[1]), "r"(a[2]), "r"(a[3]), "r"(b0), "r"(b1));
}

// ---------------------------------------------------------------------------
// Stage 1: GEMM. Grid 1024 = 512 mtiles x 2 n-halves. 256 threads.
// Per stage: A-frag 16KB, B-frag 16KB, W-raw 16.5KB (rows padded to 132 f32).
// Double-buffered: 97KB total, 2 CTAs/SM.
// ---------------------------------------------------------------------------
constexpr int OFF_B       = 16384;
constexpr int OFF_W       = 32768;
constexpr int WROW        = 132;                  // floats per padded row
constexpr int WRAW_BYTES  = 32 * WROW * 4;        // 16896
constexpr int STAGE_BYTES = OFF_W + WRAW_BYTES;   // 49664
constexpr int GEMM_SMEM   = 2 * STAGE_BYTES;      // 99328

struct ARegs { float4 lo[2], hi[2]; };  // two tasks x (row g, row g+8)

__device__ __forceinline__ void ldA(const float* __restrict__ A, int mtile,
                                    int s, int tid, ARegs& rg) {
#pragma unroll
    for (int q = 0; q < 2; ++q) {
        int tau = tid + q * 256;         // 0..511
        int cc  = tau & 7;               // col chunk (4 floats within 32-col stage)
        int pid = tau >> 3;              // 0..63
        int mtg = pid >> 3, g = pid & 7;
        const float* p = A + (size_t)(mtile * 128 + mtg * 16 + g) * 256 + s * 32 + cc * 4;
        rg.lo[q] = *(const float4*)p;
        rg.hi[q] = *(const float4*)(p + 8 * 256);
    }
}

__device__ __forceinline__ void stA(char* abuf, int tid, const ARegs& rg) {
#pragma unroll
    for (int q = 0; q < 2; ++q) {
        int tau = tid + q * 256;
        int cc  = tau & 7;
        int pid = tau >> 3;
        int mtg = pid >> 3, g = pid & 7;
        int k16l = cc >> 2;
        int kk0  = (cc & 3) * 4;
        char* blk = abuf + (mtg * 2 + k16l) * 1024;
        const float* lo = (const float*)&rg.lo[q];
        const float* hi = (const float*)&rg.hi[q];
#pragma unroll
        for (int p = 0; p < 2; ++p) {
            int kk = kk0 + 2 * p;
            int t = (kk & 7) >> 1;
            int koff = kk & 8;
            int lane = g * 4 + t;
            float v00 = lo[2 * p], v01 = lo[2 * p + 1];
            float v10 = hi[2 * p], v11 = hi[2 * p + 1];
            __half a00 = __float2half_rn(v00), a01 = __float2half_rn(v01);
            __half a10 = __float2half_rn(v10), a11 = __float2half_rn(v11);
            __half b00 = __float2half_rn(v00 - __half2float(a00));
            __half b01 = __float2half_rn(v01 - __half2float(a01));
            __half b10 = __float2half_rn(v10 - __half2float(a10));
            __half b11 = __float2half_rn(v11 - __half2float(a11));
            __half2 l0g  = __halves2half2(a00, a01);
            __half2 l0g8 = __halves2half2(a10, a11);
            __half2 l1g  = __halves2half2(b00, b01);
            __half2 l1g8 = __halves2half2(b10, b11);
            *(uint2*)(blk + lane * 16 + koff) =
                make_uint2(*(uint32_t*)&l0g, *(uint32_t*)&l0g8);
            *(uint2*)(blk + 512 + lane * 16 + koff) =
                make_uint2(*(uint32_t*)&l1g, *(uint32_t*)&l1g8);
        }
    }
}

// stage W chunk [32 k-rows x 128 n-cols] (this CTA's half) into padded smem
__device__ __forceinline__ void cpW(uint32_t wbase, const float* __restrict__ w,
                                    int h, int s, int tid) {
#pragma unroll
    for (int i = 0; i < 4; ++i) {
        int q   = tid + i * 256;         // 0..1023
        int row = q >> 5;                // 0..31
        int c16 = q & 31;                // 0..31 (16B chunks of 128-f32 row)
        const float* src = w + (size_t)(s * 32 + row) * 256 + h * 128 + c16 * 4;
        cp_async16(wbase + row * (WROW * 4) + c16 * 16, src);
    }
    cp_async_commit();
}

// convert raw W chunk -> B fragments (identical arithmetic to old prep kernel)
__device__ __forceinline__ void convB(char* sbuf, int tid) {
    const float* wraw = (const float*)(sbuf + OFF_W);
    char* bfrag = sbuf + OFF_B;
#pragma unroll
    for (int i = 0; i < 4; ++i) {
        int q = tid + i * 256;           // 0..1023: nt*64 + k16l*32 + lane
        int lane = q & 31;
        int k16l = (q >> 5) & 1;
        int nt   = q >> 6;
        int g = lane >> 2, t = lane & 3;
        int n = nt * 8 + g;
        int r0 = k16l * 16 + 2 * t;      // rows 2t, 2t+1, 2t+8, 2t+9
        float v0 = wraw[(r0 + 0) * WROW + n];
        float v1 = wraw[(r0 + 1) * WROW + n];
        float v8 = wraw[(r0 + 8) * WROW + n];
        float v9 = wraw[(r0 + 9) * WROW + n];
        __half h0a = __float2half_rn(v0), h1a = __float2half_rn(v1);
        __half h8a = __float2half_rn(v8), h9a = __float2half_rn(v9);
        __half h0b = __float2half_rn(v0 - __half2float(h0a));
        __half h1b = __float2half_rn(v1 - __half2float(h1a));
        __half h8b = __float2half_rn(v8 - __half2float(h8a));
        __half h9b = __float2half_rn(v9 - __half2float(h9a));
        __half2 l0b0 = __halves2half2(h0a, h1a);
        __half2 l0b1 = __halves2half2(h8a, h9a);
        __half2 l1b0 = __halves2half2(h0b, h1b);
        __half2 l1b1 = __halves2half2(h8b, h9b);
        uint4 frag = make_uint4(*(uint32_t*)&l0b0, *(uint32_t*)&l0b1,
                                *(uint32_t*)&l1b0, *(uint32_t*)&l1b1);
        *(uint4*)(bfrag + ((nt * 2 + k16l) * 32 + lane) * 16) = frag;
    }
}

__global__ __launch_bounds__(256, 2) void gemm_tc_kernel(
    const float* __restrict__ A, const float* __restrict__ w,
    float* __restrict__ out)
{
    extern __shared__ char smem[];
    const int tid    = threadIdx.x;
    const int wid    = tid >> 5;
    const int lane   = tid & 31;
    const int warp_m = wid & 3;        // 4 x 32 rows
    const int warp_n = wid >> 2;       // 2 x 64 cols
    const int mtile  = blockIdx.x >> 1;
    const int h      = blockIdx.x & 1;

    const uint32_t sbase = smem_u32(smem);

    float acc[2][8][4];
#pragma unroll
    for (int i = 0; i < 2; ++i)
#pragma unroll
        for (int j = 0; j < 8; ++j)
#pragma unroll
            for (int k = 0; k < 4; ++k) acc[i][j][k] = 0.0f;

    ARegs rg;
    // prologue: stage 0 raw W + A
    cpW(sbase + OFF_W, w, h, 0, tid);
    ldA(A, mtile, 0, tid, rg);
    cp_async_wait<0>();
    __syncthreads();                    // all threads' W chunks landed
    convB(smem, tid);
    stA(smem, tid, rg);
    __syncthreads();

    for (int s = 0; s < 8; ++s) {
        const int buf = s & 1;
        char* cbuf = smem + buf * STAGE_BYTES;
        char* nbuf = smem + (buf ^ 1) * STAGE_BYTES;

        if (s + 1 < 8) {
            cpW(sbase + (buf ^ 1) * STAGE_BYTES + OFF_W, w, h, s + 1, tid);
            ldA(A, mtile, s + 1, tid, rg);
        }

#pragma unroll
        for (int k16l = 0; k16l < 2; ++k16l) {
            uint4 afr[2][2];
#pragma unroll
            for (int mtl = 0; mtl < 2; ++mtl) {
                int mtg = warp_m * 2 + mtl;
                char* blk = cbuf + (mtg * 2 + k16l) * 1024;
                afr[mtl][0] = *(uint4*)(blk + lane * 16);
                afr[mtl][1] = *(uint4*)(blk + 512 + lane * 16);
            }
#pragma unroll
            for (int ng = 0; ng < 2; ++ng) {       // keep only 4 B-frags live
                uint4 bfr[4];
#pragma unroll
                for (int j = 0; j < 4; ++j) {
                    int nt = warp_n * 8 + ng * 4 + j;
                    bfr[j] = *(uint4*)(cbuf + OFF_B +
                                       ((nt * 2 + k16l) * 32 + lane) * 16);
                }
#pragma unroll
                for (int mtl = 0; mtl < 2; ++mtl)
#pragma unroll
                    for (int j = 0; j < 4; ++j) {
                        float* c = acc[mtl][ng * 4 + j];
                        mma_f16(c, (const uint32_t*)&afr[mtl][0], bfr[j].x, bfr[j].y);
                        mma_f16(c, (const uint32_t*)&afr[mtl][0], bfr[j].z, bfr[j].w);
                        mma_f16(c, (const uint32_t*)&afr[mtl][1], bfr[j].x, bfr[j].y);
                    }
            }
        }

        if (s + 1 < 8) {
            cp_async_wait<0>();         // own W(s+1) chunks done
            __syncthreads();            // everyone's chunks visible
            convB(nbuf, tid);           // writes nbuf B-frags (cbuf untouched)
            stA(nbuf, tid, rg);
        }
        __syncthreads();
    }

    // epilogue: c0=(g,2t) c1=(g,2t+1) c2=(g+8,2t) c3=(g+8,2t+1)
    const int g = lane >> 2, t = lane & 3;
#pragma unroll
    for (int mtl = 0; mtl < 2; ++mtl) {
        int row0 = mtile * 128 + warp_m * 32 + mtl * 16 + g;
#pragma unroll
        for (int ntl = 0; ntl < 8; ++ntl) {
            int col = h * 128 + warp_n * 64 + ntl * 8 + 2 * t;
            *(float2*)(out + (size_t)row0 * 256 + col) =
                make_float2(acc[mtl][ntl][0], acc[mtl][ntl][1]);
            *(float2*)(out + (size_t)(row0 + 8) * 256 + col) =
                make_float2(acc[mtl][ntl][2], acc[mtl][ntl][3]);
        }
    }
}

// ---------------------------------------------------------------------------
// Stage 2: in-place LIF scan. 256 CTAs x 64 threads (b x o-quarter),
// 3-stage cp.async pipeline (prefetch distance 2). (unchanged from R14)
// ---------------------------------------------------------------------------
constexpr int T_STEPS = 1024;
constexpr int OUT_C   = 256;
constexpr int TS      = 32;
constexpr int LPB     = 64;
constexpr int NTILES  = T_STEPS / TS;       // 32
constexpr int SPIPE   = 3;

__global__ __launch_bounds__(LPB) void lif_scan_kernel(float* __restrict__ X)
{
    __shared__ float tile[SPIPE][TS * LPB];   // 3 x 8KB

    const int tid = threadIdx.x;
    const int b   = blockIdx.x >> 2;
    const int qt  = blockIdx.x & 3;
    float* base  = X + (size_t)b * T_STEPS * OUT_C + qt * LPB;
    float* gbase = base + tid;

    uint32_t smem_base = smem_u32(&tile[0][0]);

    auto issue_tile = [&](int c, int stage) {
#pragma unroll
        for (int k = 0; k < 8; ++k) {
            int chunk = tid + k * LPB;
            int row   = chunk >> 4;
            int c16   = chunk & 15;
            const void* g = (const char*)base +
                (size_t)(c * TS + row) * OUT_C * 4 + c16 * 16;
            uint32_t s = smem_base + stage * (TS * LPB * 4) + row * (LPB * 4) + c16 * 16;
            cp_async16(s, g);
        }
        cp_async_commit();
    };

    issue_tile(0, 0);
    issue_tile(1, 1);
    issue_tile(2, 2);

    const float dcy_syn = 0.81873075307798185867f;   // exp(-0.2)
    const float dcy_mem = 0.90483741803595957316f;   // exp(-0.1)
    const float scl_mem = 1.0f - dcy_mem;

    float syn = 0.0f, mem = 0.0f;
    float carry = 0.0f;

    int stage = 0;
    for (int c = 0; c < NTILES; ++c) {
        if (c + SPIPE <= NTILES) cp_async_wait<SPIPE - 1>();
        else                     cp_async_wait<0>();
        __syncthreads();

        gbase[(size_t)(c * TS) * OUT_C] = carry;

        const float* sm = &tile[stage][tid];
#pragma unroll
        for (int i = 0; i < TS; ++i) {
            const int t = c * TS + i;
            if (t < T_STEPS - 1) {
                const float x    = sm[i * LPB];
                const float nsyn = fmaf(dcy_syn, syn, x);
                float nmem = fmaf(dcy_mem, mem, scl_mem * syn);
                if (mem > 1.0f) nmem = 0.0f;
                if (i < TS - 1)
                    gbase[(size_t)(t + 1) * OUT_C] = nmem;
                else
                    carry = nmem;
                syn = nsyn;
                mem = nmem;
            }
        }

        __syncthreads();
        if (c + SPIPE < NTILES)
            issue_tile(c + SPIPE, stage);
        stage = (stage + 1 == SPIPE) ? 0 : stage + 1;
    }
}

// ---------------------------------------------------------------------------
extern "C" void kernel_launch(void* const* d_in, const int* in_sizes, int n_in,
                              void* d_out, int out_size)
{
    const float* inputs = (const float*)d_in[0];  // [64,1024,256]
    const float* w      = (const float*)d_in[1];  // [256,256]
    float* out          = (float*)d_out;          // [64,1024,256]

    cudaFuncSetAttribute(gemm_tc_kernel,
                         cudaFuncAttributeMaxDynamicSharedMemorySize, GEMM_SMEM);

    // Stage 1: x = inputs @ w -> d_out (in-kernel W conversion, no prep)
    gemm_tc_kernel<<<1024, 256, GEMM_SMEM>>>(inputs, w, out);

    // Stage 2: in-place scan x -> U
    lif_scan_kernel<<<64 * 4, LPB>>>(out);
}

// round 16
// speedup vs baseline: 1.3923x; 1.0631x over previous
#include <cuda_runtime.h>
#include <cuda_fp16.h>
#include <cstdint>

// LIF spiking layer, monitor='mem'
//   inputs: [B=64, T=1024, IN=256] f32   (d_in[0])
//   w:      [IN=256, OUT=256] f32        (d_in[1])
//   out U:  [B=64, T=1024, OUT=256] f32  (d_out)
//
// Stage 1: 3xFP16 GEMM (f32-accum mma.sync.m16n8k16), in-kernel W conversion.
//          (unchanged from R15 — at ~95% of the HMMA issue floor)
// Stage 2: in-place LIF scan, 128 CTAs x 128 threads (single wave),
//          3-stage cp.async pipeline, full-chunk register prefetch.

// ---------------------------------------------------------------------------
// helpers
// ---------------------------------------------------------------------------
__device__ __forceinline__ void cp_async16(uint32_t smem_addr, const void* gptr) {
    asm volatile("cp.async.cg.shared.global [%0], [%1], 16;"
                 :: "r"(smem_addr), "l"(gptr) : "memory");
}
__device__ __forceinline__ void cp_async_commit() {
    asm volatile("cp.async.commit_group;" ::: "memory");
}
template <int N>
__device__ __forceinline__ void cp_async_wait() {
    asm volatile("cp.async.wait_group %0;" :: "n"(N) : "memory");
}
__device__ __forceinline__ uint32_t smem_u32(const void* p) {
    uint32_t a;
    asm("{ .reg .u64 t; cvta.to.shared.u64 t, %1; cvt.u32.u64 %0, t; }"
        : "=r"(a) : "l"(p));
    return a;
}
__device__ __forceinline__ void mma_f16(float* c, const uint32_t* a,
                                        uint32_t b0, uint32_t b1) {
    asm volatile(
        "mma.sync.aligned.m16n8k16.row.col.f32.f16.f16.f32 "
        "{%0,%1,%2,%3}, {%4,%5,%6,%7}, {%8,%9}, {%0,%1,%2,%3};"
        : "+f"(c[0]), "+f"(c[1]), "+f"(c[2]), "+f"(c[3])
        : "r"(a[0]), "r"(a[1]), "r"(a[2]), "r"(a[3]), "r"(b0), "r"(b1));
}

// ---------------------------------------------------------------------------
// Stage 1: GEMM. Grid 1024 = 512 mtiles x 2 n-halves. 256 threads.
// Per stage: A-frag 16KB, B-frag 16KB, W-raw 16.5KB (rows padded to 132 f32).
// Double-buffered: 97KB total, 2 CTAs/SM.  (unchanged from R15)
// ---------------------------------------------------------------------------
constexpr int OFF_B       = 16384;
constexpr int OFF_W       = 32768;
constexpr int WROW        = 132;
constexpr int WRAW_BYTES  = 32 * WROW * 4;        // 16896
constexpr int STAGE_BYTES = OFF_W + WRAW_BYTES;   // 49664
constexpr int GEMM_SMEM   = 2 * STAGE_BYTES;      // 99328

struct ARegs { float4 lo[2], hi[2]; };

__device__ __forceinline__ void ldA(const float* __restrict__ A, int mtile,
                                    int s, int tid, ARegs& rg) {
#pragma unroll
    for (int q = 0; q < 2; ++q) {
        int tau = tid + q * 256;
        int cc  = tau & 7;
        int pid = tau >> 3;
        int mtg = pid >> 3, g = pid & 7;
        const float* p = A + (size_t)(mtile * 128 + mtg * 16 + g) * 256 + s * 32 + cc * 4;
        rg.lo[q] = *(const float4*)p;
        rg.hi[q] = *(const float4*)(p + 8 * 256);
    }
}

__device__ __forceinline__ void stA(char* abuf, int tid, const ARegs& rg) {
#pragma unroll
    for (int q = 0; q < 2; ++q) {
        int tau = tid + q * 256;
        int cc  = tau & 7;
        int pid = tau >> 3;
        int mtg = pid >> 3, g = pid & 7;
        int k16l = cc >> 2;
        int kk0  = (cc & 3) * 4;
        char* blk = abuf + (mtg * 2 + k16l) * 1024;
        const float* lo = (const float*)&rg.lo[q];
        const float* hi = (const float*)&rg.hi[q];
#pragma unroll
        for (int p = 0; p < 2; ++p) {
            int kk = kk0 + 2 * p;
            int t = (kk & 7) >> 1;
            int koff = kk & 8;
            int lane = g * 4 + t;
            float v00 = lo[2 * p], v01 = lo[2 * p + 1];
            float v10 = hi[2 * p], v11 = hi[2 * p + 1];
            __half a00 = __float2half_rn(v00), a01 = __float2half_rn(v01);
            __half a10 = __float2half_rn(v10), a11 = __float2half_rn(v11);
            __half b00 = __float2half_rn(v00 - __half2float(a00));
            __half b01 = __float2half_rn(v01 - __half2float(a01));
            __half b10 = __float2half_rn(v10 - __half2float(a10));
            __half b11 = __float2half_rn(v11 - __half2float(a11));
            __half2 l0g  = __halves2half2(a00, a01);
            __half2 l0g8 = __halves2half2(a10, a11);
            __half2 l1g  = __halves2half2(b00, b01);
            __half2 l1g8 = __halves2half2(b10, b11);
            *(uint2*)(blk + lane * 16 + koff) =
                make_uint2(*(uint32_t*)&l0g, *(uint32_t*)&l0g8);
            *(uint2*)(blk + 512 + lane * 16 + koff) =
                make_uint2(*(uint32_t*)&l1g, *(uint32_t*)&l1g8);
        }
    }
}

__device__ __forceinline__ void cpW(uint32_t wbase, const float* __restrict__ w,
                                    int h, int s, int tid) {
#pragma unroll
    for (int i = 0; i < 4; ++i) {
        int q   = tid + i * 256;
        int row = q >> 5;
        int c16 = q & 31;
        const float* src = w + (size_t)(s * 32 + row) * 256 + h * 128 + c16 * 4;
        cp_async16(wbase + row * (WROW * 4) + c16 * 16, src);
    }
    cp_async_commit();
}

__device__ __forceinline__ void convB(char* sbuf, int tid) {
    const float* wraw = (const float*)(sbuf + OFF_W);
    char* bfrag = sbuf + OFF_B;
#pragma unroll
    for (int i = 0; i < 4; ++i) {
        int q = tid + i * 256;
        int lane = q & 31;
        int k16l = (q >> 5) & 1;
        int nt   = q >> 6;
        int g = lane >> 2, t = lane & 3;
        int n = nt * 8 + g;
        int r0 = k16l * 16 + 2 * t;
        float v0 = wraw[(r0 + 0) * WROW + n];
        float v1 = wraw[(r0 + 1) * WROW + n];
        float v8 = wraw[(r0 + 8) * WROW + n];
        float v9 = wraw[(r0 + 9) * WROW + n];
        __half h0a = __float2half_rn(v0), h1a = __float2half_rn(v1);
        __half h8a = __float2half_rn(v8), h9a = __float2half_rn(v9);
        __half h0b = __float2half_rn(v0 - __half2float(h0a));
        __half h1b = __float2half_rn(v1 - __half2float(h1a));
        __half h8b = __float2half_rn(v8 - __half2float(h8a));
        __half h9b = __float2half_rn(v9 - __half2float(h9a));
        __half2 l0b0 = __halves2half2(h0a, h1a);
        __half2 l0b1 = __halves2half2(h8a, h9a);
        __half2 l1b0 = __halves2half2(h0b, h1b);
        __half2 l1b1 = __halves2half2(h8b, h9b);
        uint4 frag = make_uint4(*(uint32_t*)&l0b0, *(uint32_t*)&l0b1,
                                *(uint32_t*)&l1b0, *(uint32_t*)&l1b1);
        *(uint4*)(bfrag + ((nt * 2 + k16l) * 32 + lane) * 16) = frag;
    }
}

__global__ __launch_bounds__(256, 2) void gemm_tc_kernel(
    const float* __restrict__ A, const float* __restrict__ w,
    float* __restrict__ out)
{
    extern __shared__ char smem[];
    const int tid    = threadIdx.x;
    const int wid    = tid >> 5;
    const int lane   = tid & 31;
    const int warp_m = wid & 3;
    const int warp_n = wid >> 2;
    const int mtile  = blockIdx.x >> 1;
    const int h      = blockIdx.x & 1;

    const uint32_t sbase = smem_u32(smem);

    float acc[2][8][4];
#pragma unroll
    for (int i = 0; i < 2; ++i)
#pragma unroll
        for (int j = 0; j < 8; ++j)
#pragma unroll
            for (int k = 0; k < 4; ++k) acc[i][j][k] = 0.0f;

    ARegs rg;
    cpW(sbase + OFF_W, w, h, 0, tid);
    ldA(A, mtile, 0, tid, rg);
    cp_async_wait<0>();
    __syncthreads();
    convB(smem, tid);
    stA(smem, tid, rg);
    __syncthreads();

    for (int s = 0; s < 8; ++s) {
        const int buf = s & 1;
        char* cbuf = smem + buf * STAGE_BYTES;
        char* nbuf = smem + (buf ^ 1) * STAGE_BYTES;

        if (s + 1 < 8) {
            cpW(sbase + (buf ^ 1) * STAGE_BYTES + OFF_W, w, h, s + 1, tid);
            ldA(A, mtile, s + 1, tid, rg);
        }

#pragma unroll
        for (int k16l = 0; k16l < 2; ++k16l) {
            uint4 afr[2][2];
#pragma unroll
            for (int mtl = 0; mtl < 2; ++mtl) {
                int mtg = warp_m * 2 + mtl;
                char* blk = cbuf + (mtg * 2 + k16l) * 1024;
                afr[mtl][0] = *(uint4*)(blk + lane * 16);
                afr[mtl][1] = *(uint4*)(blk + 512 + lane * 16);
            }
#pragma unroll
            for (int ng = 0; ng < 2; ++ng) {
                uint4 bfr[4];
#pragma unroll
                for (int j = 0; j < 4; ++j) {
                    int nt = warp_n * 8 + ng * 4 + j;
                    bfr[j] = *(uint4*)(cbuf + OFF_B +
                                       ((nt * 2 + k16l) * 32 + lane) * 16);
                }
#pragma unroll
                for (int mtl = 0; mtl < 2; ++mtl)
#pragma unroll
                    for (int j = 0; j < 4; ++j) {
                        float* c = acc[mtl][ng * 4 + j];
                        mma_f16(c, (const uint32_t*)&afr[mtl][0], bfr[j].x, bfr[j].y);
                        mma_f16(c, (const uint32_t*)&afr[mtl][0], bfr[j].z, bfr[j].w);
                        mma_f16(c, (const uint32_t*)&afr[mtl][1], bfr[j].x, bfr[j].y);
                    }
            }
        }

        if (s + 1 < 8) {
            cp_async_wait<0>();
            __syncthreads();
            convB(nbuf, tid);
            stA(nbuf, tid, rg);
        }
        __syncthreads();
    }

    const int g = lane >> 2, t = lane & 3;
#pragma unroll
    for (int mtl = 0; mtl < 2; ++mtl) {
        int row0 = mtile * 128 + warp_m * 32 + mtl * 16 + g;
#pragma unroll
        for (int ntl = 0; ntl < 8; ++ntl) {
            int col = h * 128 + warp_n * 64 + ntl * 8 + 2 * t;
            *(float2*)(out + (size_t)row0 * 256 + col) =
                make_float2(acc[mtl][ntl][0], acc[mtl][ntl][1]);
            *(float2*)(out + (size_t)(row0 + 8) * 256 + col) =
                make_float2(acc[mtl][ntl][2], acc[mtl][ntl][3]);
        }
    }
}

// ---------------------------------------------------------------------------
// Stage 2: in-place LIF scan.
// 128 CTAs x 128 threads (b x o-half) — SINGLE wave on 148 SMs.
// 3-stage cp.async pipeline; whole 32-step chunk prefetched into registers
// so LDS latency never sits on the serial state chain.
// ---------------------------------------------------------------------------
constexpr int T_STEPS = 1024;
constexpr int OUT_C   = 256;
constexpr int TS      = 32;
constexpr int LPB     = 128;                // lanes per block
constexpr int NTILES  = T_STEPS / TS;       // 32
constexpr int SPIPE   = 3;

__global__ __launch_bounds__(LPB) void lif_scan_kernel(float* __restrict__ X)
{
    __shared__ float tile[SPIPE][TS * LPB];   // 3 x 16KB

    const int tid  = threadIdx.x;
    const int b    = blockIdx.x >> 1;
    const int half = blockIdx.x & 1;
    float* base  = X + (size_t)b * T_STEPS * OUT_C + half * LPB;
    float* gbase = base + tid;

    uint32_t smem_base = smem_u32(&tile[0][0]);

    // per tile: 32 rows x 32 x 16B chunks = 1024 chunks, 128 threads x 8
    auto issue_tile = [&](int c, int stage) {
#pragma unroll
        for (int k = 0; k < 8; ++k) {
            int chunk = tid + k * LPB;
            int row   = chunk >> 5;
            int c16   = chunk & 31;
            const void* g = (const char*)base +
                (size_t)(c * TS + row) * OUT_C * 4 + c16 * 16;
            uint32_t s = smem_base + stage * (TS * LPB * 4) + row * (LPB * 4) + c16 * 16;
            cp_async16(s, g);
        }
        cp_async_commit();
    };

    issue_tile(0, 0);
    issue_tile(1, 1);
    issue_tile(2, 2);

    const float dcy_syn = 0.81873075307798185867f;   // exp(-0.2)
    const float dcy_mem = 0.90483741803595957316f;   // exp(-0.1)
    const float scl_mem = 1.0f - dcy_mem;

    float syn = 0.0f, mem = 0.0f;
    float carry = 0.0f;

    int stage = 0;
    for (int c = 0; c < NTILES; ++c) {
        if (c + SPIPE <= NTILES) cp_async_wait<SPIPE - 1>();
        else                     cp_async_wait<0>();
        __syncthreads();

        gbase[(size_t)(c * TS) * OUT_C] = carry;

        const float* sm = &tile[stage][tid];

        // pull the whole chunk into registers first: LDS latency off the chain
        float xv[TS];
#pragma unroll
        for (int i = 0; i < TS; ++i) xv[i] = sm[i * LPB];

#pragma unroll
        for (int i = 0; i < TS; ++i) {
            const int t = c * TS + i;
            if (t < T_STEPS - 1) {
                const float nsyn = fmaf(dcy_syn, syn, xv[i]);
                float nmem = fmaf(dcy_mem, mem, scl_mem * syn);
                if (mem > 1.0f) nmem = 0.0f;
                if (i < TS - 1)
                    gbase[(size_t)(t + 1) * OUT_C] = nmem;
                else
                    carry = nmem;
                syn = nsyn;
                mem = nmem;
            }
        }

        __syncthreads();
        if (c + SPIPE < NTILES)
            issue_tile(c + SPIPE, stage);
        stage = (stage + 1 == SPIPE) ? 0 : stage + 1;
    }
}

// ---------------------------------------------------------------------------
extern "C" void kernel_launch(void* const* d_in, const int* in_sizes, int n_in,
                              void* d_out, int out_size)
{
    const float* inputs = (const float*)d_in[0];  // [64,1024,256]
    const float* w      = (const float*)d_in[1];  // [256,256]
    float* out          = (float*)d_out;          // [64,1024,256]

    cudaFuncSetAttribute(gemm_tc_kernel,
                         cudaFuncAttributeMaxDynamicSharedMemorySize, GEMM_SMEM);

    // Stage 1: x = inputs @ w -> d_out (in-kernel W conversion)
    gemm_tc_kernel<<<1024, 256, GEMM_SMEM>>>(inputs, w, out);

    // Stage 2: in-place scan x -> U (128 CTAs = 64 batches x 2 halves)
    lif_scan_kernel<<<64 * 2, LPB>>>(out);
}